// round 13
// baseline (speedup 1.0000x reference)
#include <cuda_runtime.h>
#include <math_constants.h>

#define BT 16
#define VH 6890
#define VO 2048
#define NH (BT*VH)          /* 110240 */
#define NO (BT*VO)          /* 32768  */
#define TPB 256
#define RPT 4
#define ROWCHUNK (TPB*RPT)  /* 1024 */
#define RCHUNKS ((VH+ROWCHUNK-1)/ROWCHUNK)  /* 7 */
#define JT 256
#define J2 (JT/2)           /* 128 packed object-pairs */
#define JCHUNKS (VO/JT)     /* 8 */

#define INF_BITS 0x7F800000u

// Scratch (static __device__ — no allocations allowed).
// Min arrays store KEY = 0x7F800000 - d2_bits, reduced with atomicMax (REDG.MAX).
// key==0 decodes to d2=+inf -> CUDA zero-init of __device__ globals is the identity
// state. k_loss re-arms each element to 0 after reading it (sole reader/writer),
// so every graph replay starts from the identity. No init kernel.
__device__ unsigned g_dh[2*NH];     // row keys  [ds][b][i]
__device__ unsigned g_do[2*NO];     // col keys  [ds][b][j]
__device__ double   g_acc[8];       // [dir(h/o)][P, Spos, Sneg, Shub]
__device__ unsigned g_done;

// ---- packed f32x2 helpers (Blackwell FFMA2 path) ----
union F2U { float2 f; unsigned long long u; };

__device__ __forceinline__ float2 fma2(float2 a, float2 b, float2 c) {
    F2U A, B, C, D; A.f = a; B.f = b; C.f = c;
    asm("fma.rn.f32x2 %0, %1, %2, %3;" : "=l"(D.u) : "l"(A.u), "l"(B.u), "l"(C.u));
    return D.f;
}
__device__ __forceinline__ float2 add2(float2 a, float2 b) {
    F2U A, B, D; A.f = a; B.f = b;
    asm("add.rn.f32x2 %0, %1, %2;" : "=l"(A.u) : "l"(A.u), "l"(B.u));
    return A.f;
}

// clamp negative-d2 bit patterns to 0 (== reference max(d2,0)), then encode
__device__ __forceinline__ unsigned d2bits_to_key(unsigned bits) {
    bits = (bits >= 0x80000000u) ? 0u : bits;
    return INF_BITS - bits;
}

__global__ void __launch_bounds__(TPB) k_pair(const float* __restrict__ h,
                                              const float* __restrict__ o,
                                              const float* __restrict__ gh,
                                              const float* __restrict__ go) {
    __shared__ float4   sP[J2];   // {ox.x, ox.y, oy.x, oy.y} (two objects packed, pre-negated *2)
    __shared__ float4   sQ[J2];   // {oz.x, oz.y, ow.x, ow.y}
    __shared__ unsigned sCol[JT];
    const int ds = blockIdx.z, b = blockIdx.y;
    const int rc = blockIdx.x / JCHUNKS, jc = blockIdx.x % JCHUNKS;
    const int t  = threadIdx.x;

    // zero the loss accumulators once per launch (k_loss runs strictly after)
    if (blockIdx.x == 0 && b == 0 && ds == 0) {
        if (t < 8)  g_acc[t] = 0.0;
        if (t == 8) g_done = 0u;
    }

    // stage objects directly from raw input: obj tile is 256*3 contiguous floats
    const float* OB = (ds ? go : o) + (size_t)(b * VO + jc * JT) * 3;
    if (t < J2) {
        const float2* p2 = (const float2*)(OB + 6 * t);   // 8B-aligned
        float2 f0 = p2[0], f1 = p2[1], f2 = p2[2];        // [xA yA | zA xB | yB zB]
        float xA = f0.x, yA = f0.y, zA = f1.x;
        float xB = f1.y, yB = f2.x, zB = f2.y;
        float wA = fmaf(xA, xA, fmaf(yA, yA, zA * zA));
        float wB = fmaf(xB, xB, fmaf(yB, yB, zB * zB));
        sP[t] = make_float4(-2.f*xA, -2.f*xB, -2.f*yA, -2.f*yB);
        sQ[t] = make_float4(-2.f*zA, -2.f*zB, wA, wB);
    }
    sCol[t] = 0x7F800000u;

    const float* H = (ds ? gh : h) + (size_t)b * VH * 3;
    float2 hx2[RPT], hy2[RPT], hz2[RPT], hh2[RPT];
    float rA[RPT], rB[RPT];   // per-half row-min accumulators (q-space)
    const int row0 = rc * ROWCHUNK + t;
#pragma unroll
    for (int k = 0; k < RPT; k++) {
        int row = row0 + k * TPB;
        float x = 0.f, y = 0.f, z = 0.f, s = CUDART_INF_F;
        if (row < VH) {
            x = H[row*3+0]; y = H[row*3+1]; z = H[row*3+2];
            s = fmaf(x, x, fmaf(y, y, z*z));
        }
        hx2[k] = make_float2(x, x);
        hy2[k] = make_float2(y, y);
        hz2[k] = make_float2(z, z);
        hh2[k] = make_float2(s, s);   // +inf for invalid rows -> never wins col-min
        rA[k] = CUDART_INF_F; rB[k] = CUDART_INF_F;
    }
    __syncthreads();

#define UNR 4
#pragma unroll 1
    for (int j0 = 0; j0 < J2; j0 += UNR) {
        // batch smem loads: 2 LDS.128 per j2 (operand pairs usable directly as f32x2)
        float4 vP[UNR], vQ[UNR];
#pragma unroll
        for (int u = 0; u < UNR; u++) { vP[u] = sP[j0+u]; vQ[u] = sQ[j0+u]; }
#pragma unroll
        for (int u = 0; u < UNR; u++) {
            float2 ox = make_float2(vP[u].x, vP[u].y);
            float2 oy = make_float2(vP[u].z, vP[u].w);
            float2 oz = make_float2(vQ[u].x, vQ[u].y);
            float2 ow = make_float2(vQ[u].z, vQ[u].w);
            float cmA = CUDART_INF_F, cmB = CUDART_INF_F;
#pragma unroll
            for (int k = 0; k < RPT; k++) {
                float2 q2 = fma2(hz2[k], oz, ow);   // oo - 2 h·o (two objects)
                q2 = fma2(hy2[k], oy, q2);
                q2 = fma2(hx2[k], ox, q2);
                rA[k] = fminf(rA[k], q2.x);         // row-min in q-space
                rB[k] = fminf(rB[k], q2.y);
                float2 c2 = add2(q2, hh2[k]);       // full d^2 for col-min
                cmA = fminf(cmA, c2.x);
                cmB = fminf(cmB, c2.y);
            }
            // clamp >=0: uint order == float order for the min reductions
            unsigned uA = __reduce_min_sync(0xFFFFFFFFu, __float_as_uint(fmaxf(cmA, 0.f)));
            unsigned uB = __reduce_min_sync(0xFFFFFFFFu, __float_as_uint(fmaxf(cmB, 0.f)));
            if ((t & 31) == 0) {
                atomicMin(&sCol[2*(j0+u)],     uA);
                atomicMin(&sCol[2*(j0+u) + 1], uB);
            }
        }
    }
    __syncthreads();

    // push mins as keys via fire-and-forget REDG.MAX (zero state = identity)
    atomicMax(&g_do[ds*NO + b*VO + jc*JT + t], d2bits_to_key(sCol[t]));
#pragma unroll
    for (int k = 0; k < RPT; k++) {
        int row = row0 + k * TPB;
        if (row < VH) {
            float d2 = fmaxf(fminf(rA[k], rB[k]) + hh2[k].x, 0.f);
            atomicMax(&g_dh[ds*NH + b*VH + row], d2bits_to_key(__float_as_uint(d2)));
        }
    }
}

#define LOSS_BLOCKS 192

__global__ void k_loss(float* out) {
    const int dir = blockIdx.y;          // 0 = human rows, 1 = object cols
    const int N   = dir ? NO : NH;       // both even
    unsigned* arr = dir ? g_do : g_dh;
    const int  NN = dir ? NO : NH;
    float P = 0.f, Spos = 0.f, Sneg = 0.f, Shub = 0.f;
    // two adjacent elements per iteration; __ldg (non-coherent path) decouples the
    // loads from the re-arm stores below -> full MLP, no alias serialization.
    for (int i2 = blockIdx.x * blockDim.x + threadIdx.x; i2 < N/2;
         i2 += LOSS_BLOCKS * blockDim.x) {
        uint2 pv = __ldg((const uint2*)&arr[2*i2]);
        uint2 gv = __ldg((const uint2*)&arr[NN + 2*i2]);
        ((uint2*)&arr[2*i2])[0]      = make_uint2(0u, 0u);   // re-arm for next replay
        ((uint2*)&arr[NN + 2*i2])[0] = make_uint2(0u, 0u);
#pragma unroll
        for (int e = 0; e < 2; e++) {
            unsigned kp = e ? pv.y : pv.x, kg = e ? gv.y : gv.x;
            float pd = sqrtf(__uint_as_float(INF_BITS - kp));  // key 0 -> +inf (clamped rows only exist if VH pad; fine)
            float gd = sqrtf(__uint_as_float(INF_BITS - kg));
            bool tpos = gd < 0.2f;
            float z = (0.2f - pd) * 100.f;
            // -log(clip(sigmoid(z))) == clamp(log1p(exp(-z)), 1e-6, -log(1e-6))
            float w = tpos ? -z : z;
            float l = log1pf(expf(w));
            l = fminf(fmaxf(l, 1e-6f), 13.8155106f);
            if (tpos) { P += 1.f; Spos += l; } else { Sneg += l; }
            float over = fmaxf(pd - 0.1f, 0.f);
            float hub  = (over < 0.01f) ? (50.f * over * over) : (over - 0.005f);
            if (tpos) Shub += hub;
        }
    }
#pragma unroll
    for (int off = 16; off; off >>= 1) {
        P    += __shfl_down_sync(0xFFFFFFFFu, P,    off);
        Spos += __shfl_down_sync(0xFFFFFFFFu, Spos, off);
        Sneg += __shfl_down_sync(0xFFFFFFFFu, Sneg, off);
        Shub += __shfl_down_sync(0xFFFFFFFFu, Shub, off);
    }
    __shared__ float s[4][8];
    int w = threadIdx.x >> 5, l = threadIdx.x & 31;
    if (l == 0) { s[0][w] = P; s[1][w] = Spos; s[2][w] = Sneg; s[3][w] = Shub; }
    __syncthreads();
    if (threadIdx.x == 0) {
        float a0 = 0, a1 = 0, a2 = 0, a3 = 0;
        int nw = (blockDim.x + 31) >> 5;
        for (int k = 0; k < nw; k++) { a0 += s[0][k]; a1 += s[1][k]; a2 += s[2][k]; a3 += s[3][k]; }
        atomicAdd(&g_acc[dir*4 + 0], (double)a0);
        atomicAdd(&g_acc[dir*4 + 1], (double)a1);
        atomicAdd(&g_acc[dir*4 + 2], (double)a2);
        atomicAdd(&g_acc[dir*4 + 3], (double)a3);
        __threadfence();
        unsigned v = atomicAdd(&g_done, 1u);
        if (v == 2*LOSS_BLOCKS - 1) {    // last block: finalize
            double Ph = g_acc[0], Sph = g_acc[1], Snh = g_acc[2], Shh = g_acc[3];
            double Po = g_acc[4], Spo = g_acc[5], Sno = g_acc[6], Sho = g_acc[7];
            double negh = (double)NH - Ph, nego = (double)NO - Po;
            double pwh = (negh + 1e-6) / (Ph + 1e-6);
            double pwo = (nego + 1e-6) / (Po + 1e-6);
            double bh = (pwh * Sph + Snh) / (double)NH;
            double bo = (pwo * Spo + Sno) / (double)NO;
            double Lbce = 0.5 * (bh + bo);
            double LhH = (Ph > 0.0) ? (Shh / fmax(Ph, 1.0)) : 0.0;
            double LhO = (Po > 0.0) ? (Sho / fmax(Po, 1.0)) : 0.0;
            out[0] = (float)(0.5 * Lbce + (LhH + LhO));
        }
    }
}

extern "C" void kernel_launch(void* const* d_in, const int* in_sizes, int n_in,
                              void* d_out, int out_size) {
    const float* h  = (const float*)d_in[0];
    const float* o  = (const float*)d_in[1];
    const float* gh = (const float*)d_in[2];
    const float* go = (const float*)d_in[3];

    dim3 gp(RCHUNKS * JCHUNKS, BT, 2);              // 56 x 16 x 2 = 1792 blocks
    k_pair<<<gp, TPB>>>(h, o, gh, go);
    dim3 gl(LOSS_BLOCKS, 2);
    k_loss<<<gl, 256>>>((float*)d_out);
}

// round 14
// speedup vs baseline: 1.0501x; 1.0501x over previous
#include <cuda_runtime.h>
#include <math_constants.h>

#define BT 16
#define VH 6890
#define VO 2048
#define NH (BT*VH)          /* 110240 */
#define NO (BT*VO)          /* 32768  */
#define TPB 256
#define NW  (TPB/32)        /* 8 warps */
#define RPT 4
#define ROWCHUNK (TPB*RPT)  /* 1024 */
#define RCHUNKS ((VH+ROWCHUNK-1)/ROWCHUNK)  /* 7 */
#define JT 256
#define J2 (JT/2)           /* 128 packed object-pairs */
#define JCHUNKS (VO/JT)     /* 8 */

// Scratch (static __device__ — no allocations allowed)
__device__ unsigned g_dh[2*NH];     // min d^2 bits, human rows  [ds][b][i]
__device__ unsigned g_do[2*NO];     // min d^2 bits, object cols [ds][b][j]
__device__ double   g_acc[8];       // [dir(h/o)][P, Spos, Sneg, Shub]
__device__ unsigned g_done;

// ---- packed f32x2 helpers (Blackwell FFMA2 path) ----
union F2U { float2 f; unsigned long long u; };

__device__ __forceinline__ float2 fma2(float2 a, float2 b, float2 c) {
    F2U A, B, C, D; A.f = a; B.f = b; C.f = c;
    asm("fma.rn.f32x2 %0, %1, %2, %3;" : "=l"(D.u) : "l"(A.u), "l"(B.u), "l"(C.u));
    return D.f;
}
__device__ __forceinline__ float2 add2(float2 a, float2 b) {
    F2U A, B, D; A.f = a; B.f = b;
    asm("add.rn.f32x2 %0, %1, %2;" : "=l"(D.u) : "l"(A.u), "l"(B.u));
    return D.f;
}

// pure memset-style init: uint4 wide fills, nothing else
__global__ void k_init() {
    int i = blockIdx.x * blockDim.x + threadIdx.x;
    const unsigned INF = 0x7F800000u;
    if (i < (2*NH)/4) ((uint4*)g_dh)[i] = make_uint4(INF, INF, INF, INF);  // 55120
    if (i < (2*NO)/4) ((uint4*)g_do)[i] = make_uint4(INF, INF, INF, INF);  // 16384
    if (i < 8)  g_acc[i] = 0.0;
    if (i == 8) g_done = 0u;
}

__global__ void __launch_bounds__(TPB) k_pair(const float* __restrict__ h,
                                              const float* __restrict__ o,
                                              const float* __restrict__ gh,
                                              const float* __restrict__ go) {
    __shared__ float4   sP[J2];       // {ox.x, ox.y, oy.x, oy.y} (two objects packed, pre-negated *2)
    __shared__ float4   sQ[J2];       // {oz.x, oz.y, ow.x, ow.y}
    __shared__ unsigned sColW[NW][JT]; // per-warp column mins: plain STS, no atomics
    const int ds = blockIdx.z, b = blockIdx.y;
    const int rc = blockIdx.x / JCHUNKS, jc = blockIdx.x % JCHUNKS;
    const int t  = threadIdx.x;
    const int w  = t >> 5;

    // stage objects directly from raw input: obj tile is 256*3 contiguous floats
    const float* OB = (ds ? go : o) + (size_t)(b * VO + jc * JT) * 3;
    if (t < J2) {
        const float2* p2 = (const float2*)(OB + 6 * t);   // 8B-aligned
        float2 f0 = p2[0], f1 = p2[1], f2 = p2[2];        // [xA yA | zA xB | yB zB]
        float xA = f0.x, yA = f0.y, zA = f1.x;
        float xB = f1.y, yB = f2.x, zB = f2.y;
        float wA = fmaf(xA, xA, fmaf(yA, yA, zA * zA));
        float wB = fmaf(xB, xB, fmaf(yB, yB, zB * zB));
        sP[t] = make_float4(-2.f*xA, -2.f*xB, -2.f*yA, -2.f*yB);
        sQ[t] = make_float4(-2.f*zA, -2.f*zB, wA, wB);
    }

    const float* H = (ds ? gh : h) + (size_t)b * VH * 3;
    float2 hx2[RPT], hy2[RPT], hz2[RPT], hh2[RPT];
    float rA[RPT], rB[RPT];   // per-half row-min accumulators (q-space)
    const int row0 = rc * ROWCHUNK + t;
#pragma unroll
    for (int k = 0; k < RPT; k++) {
        int row = row0 + k * TPB;
        float x = 0.f, y = 0.f, z = 0.f, s = CUDART_INF_F;
        if (row < VH) {
            x = H[row*3+0]; y = H[row*3+1]; z = H[row*3+2];
            s = fmaf(x, x, fmaf(y, y, z*z));
        }
        hx2[k] = make_float2(x, x);
        hy2[k] = make_float2(y, y);
        hz2[k] = make_float2(z, z);
        hh2[k] = make_float2(s, s);   // +inf for invalid rows -> never wins col-min
        rA[k] = CUDART_INF_F; rB[k] = CUDART_INF_F;
    }
    __syncthreads();

#define UNR 4
#pragma unroll 1
    for (int j0 = 0; j0 < J2; j0 += UNR) {
        // batch smem loads: 2 LDS.128 per j2 (operand pairs usable directly as f32x2)
        float4 vP[UNR], vQ[UNR];
#pragma unroll
        for (int u = 0; u < UNR; u++) { vP[u] = sP[j0+u]; vQ[u] = sQ[j0+u]; }
#pragma unroll
        for (int u = 0; u < UNR; u++) {
            float2 ox = make_float2(vP[u].x, vP[u].y);
            float2 oy = make_float2(vP[u].z, vP[u].w);
            float2 oz = make_float2(vQ[u].x, vQ[u].y);
            float2 ow = make_float2(vQ[u].z, vQ[u].w);
            float cmA = CUDART_INF_F, cmB = CUDART_INF_F;
#pragma unroll
            for (int k = 0; k < RPT; k++) {
                float2 q2 = fma2(hz2[k], oz, ow);   // oo - 2 h·o (two objects)
                q2 = fma2(hy2[k], oy, q2);
                q2 = fma2(hx2[k], ox, q2);
                rA[k] = fminf(rA[k], q2.x);         // row-min in q-space
                rB[k] = fminf(rB[k], q2.y);
                float2 c2 = add2(q2, hh2[k]);       // full d^2 for col-min
                cmA = fminf(cmA, c2.x);
                cmB = fminf(cmB, c2.y);
            }
            // clamp >=0: uint order == float order for the min reductions
            unsigned uA = __reduce_min_sync(0xFFFFFFFFu, __float_as_uint(fmaxf(cmA, 0.f)));
            unsigned uB = __reduce_min_sync(0xFFFFFFFFu, __float_as_uint(fmaxf(cmB, 0.f)));
            if ((t & 31) == 0) {                    // plain STS into this warp's slot
                sColW[w][2*(j0+u)]     = uA;
                sColW[w][2*(j0+u) + 1] = uB;
            }
        }
    }
    __syncthreads();

    // epilogue: combine the 8 warp slots per column (conflict-free LDS + IMNMX),
    // then push mins; unused return value -> fire-and-forget REDG.MIN
    {
        unsigned m = sColW[0][t];
#pragma unroll
        for (int ww = 1; ww < NW; ww++) m = min(m, sColW[ww][t]);
        atomicMin(&g_do[ds*NO + b*VO + jc*JT + t], m);
    }
#pragma unroll
    for (int k = 0; k < RPT; k++) {
        int row = row0 + k * TPB;
        if (row < VH) {
            float d2 = fmaxf(fminf(rA[k], rB[k]) + hh2[k].x, 0.f);
            atomicMin(&g_dh[ds*NH + b*VH + row], __float_as_uint(d2));
        }
    }
}

#define LOSS_BLOCKS 128

__global__ void k_loss(float* out) {
    const int dir = blockIdx.y;          // 0 = human rows, 1 = object cols
    const int N   = dir ? NO : NH;       // both even
    const unsigned* arr = dir ? g_do : g_dh;
    const int  NN = dir ? NO : NH;
    float P = 0.f, Spos = 0.f, Sneg = 0.f, Shub = 0.f;
    // two adjacent elements per iteration via uint2 loads (read-only)
    for (int i2 = blockIdx.x * blockDim.x + threadIdx.x; i2 < N/2;
         i2 += LOSS_BLOCKS * blockDim.x) {
        uint2 pv = __ldg((const uint2*)&arr[2*i2]);
        uint2 gv = __ldg((const uint2*)&arr[NN + 2*i2]);
#pragma unroll
        for (int e = 0; e < 2; e++) {
            unsigned pb = e ? pv.y : pv.x, gb = e ? gv.y : gv.x;
            float pd = sqrtf(fmaxf(__uint_as_float(pb), 0.f));
            float gd = sqrtf(fmaxf(__uint_as_float(gb), 0.f));
            bool tpos = gd < 0.2f;
            float z = (0.2f - pd) * 100.f;
            // -log(clip(sigmoid(z))) == clamp(log1p(exp(-z)), 1e-6, -log(1e-6))
            float wv = tpos ? -z : z;
            float l = log1pf(expf(wv));
            l = fminf(fmaxf(l, 1e-6f), 13.8155106f);
            if (tpos) { P += 1.f; Spos += l; } else { Sneg += l; }
            float over = fmaxf(pd - 0.1f, 0.f);
            float hub  = (over < 0.01f) ? (50.f * over * over) : (over - 0.005f);
            if (tpos) Shub += hub;
        }
    }
#pragma unroll
    for (int off = 16; off; off >>= 1) {
        P    += __shfl_down_sync(0xFFFFFFFFu, P,    off);
        Spos += __shfl_down_sync(0xFFFFFFFFu, Spos, off);
        Sneg += __shfl_down_sync(0xFFFFFFFFu, Sneg, off);
        Shub += __shfl_down_sync(0xFFFFFFFFu, Shub, off);
    }
    __shared__ float s[4][8];
    int w = threadIdx.x >> 5, l = threadIdx.x & 31;
    if (l == 0) { s[0][w] = P; s[1][w] = Spos; s[2][w] = Sneg; s[3][w] = Shub; }
    __syncthreads();
    if (threadIdx.x == 0) {
        float a0 = 0, a1 = 0, a2 = 0, a3 = 0;
        int nw = (blockDim.x + 31) >> 5;
        for (int k = 0; k < nw; k++) { a0 += s[0][k]; a1 += s[1][k]; a2 += s[2][k]; a3 += s[3][k]; }
        atomicAdd(&g_acc[dir*4 + 0], (double)a0);
        atomicAdd(&g_acc[dir*4 + 1], (double)a1);
        atomicAdd(&g_acc[dir*4 + 2], (double)a2);
        atomicAdd(&g_acc[dir*4 + 3], (double)a3);
        __threadfence();
        unsigned v = atomicAdd(&g_done, 1u);
        if (v == 2*LOSS_BLOCKS - 1) {    // last block: finalize
            double Ph = g_acc[0], Sph = g_acc[1], Snh = g_acc[2], Shh = g_acc[3];
            double Po = g_acc[4], Spo = g_acc[5], Sno = g_acc[6], Sho = g_acc[7];
            double negh = (double)NH - Ph, nego = (double)NO - Po;
            double pwh = (negh + 1e-6) / (Ph + 1e-6);
            double pwo = (nego + 1e-6) / (Po + 1e-6);
            double bh = (pwh * Sph + Snh) / (double)NH;
            double bo = (pwo * Spo + Sno) / (double)NO;
            double Lbce = 0.5 * (bh + bo);
            double LhH = (Ph > 0.0) ? (Shh / fmax(Ph, 1.0)) : 0.0;
            double LhO = (Po > 0.0) ? (Sho / fmax(Po, 1.0)) : 0.0;
            out[0] = (float)(0.5 * Lbce + (LhH + LhO));
        }
    }
}

extern "C" void kernel_launch(void* const* d_in, const int* in_sizes, int n_in,
                              void* d_out, int out_size) {
    const float* h  = (const float*)d_in[0];
    const float* o  = (const float*)d_in[1];
    const float* gh = (const float*)d_in[2];
    const float* go = (const float*)d_in[3];

    k_init<<<((2*NH)/4 + 255)/256, 256>>>();        // 216 blocks, pure fills
    dim3 gp(RCHUNKS * JCHUNKS, BT, 2);              // 56 x 16 x 2 = 1792 blocks
    k_pair<<<gp, TPB>>>(h, o, gh, go);
    dim3 gl(LOSS_BLOCKS, 2);
    k_loss<<<gl, 256>>>((float*)d_out);
}

// round 15
// speedup vs baseline: 1.1520x; 1.0971x over previous
#include <cuda_runtime.h>
#include <math_constants.h>

#define BT 16
#define VH 6890
#define VO 2048
#define NH (BT*VH)          /* 110240 */
#define NO (BT*VO)          /* 32768  */
#define TPB 128
#define NW  (TPB/32)        /* 4 warps */
#define RPT 4
#define ROWCHUNK (TPB*RPT)  /* 512 */
#define RCHUNKS ((VH+ROWCHUNK-1)/ROWCHUNK)  /* 14 */
#define JT 256
#define J2 (JT/2)           /* 128 packed object-pairs; == TPB */
#define JCHUNKS (VO/JT)     /* 8 */

// Scratch (static __device__ — no allocations allowed)
__device__ unsigned g_dh[2*NH];     // min d^2 bits, human rows  [ds][b][i]
__device__ unsigned g_do[2*NO];     // min d^2 bits, object cols [ds][b][j]
__device__ double   g_acc[8];       // [dir(h/o)][P, Spos, Sneg, Shub]
__device__ unsigned g_done;

// ---- packed f32x2 helpers (Blackwell FFMA2 path) ----
union F2U { float2 f; unsigned long long u; };

__device__ __forceinline__ float2 fma2(float2 a, float2 b, float2 c) {
    F2U A, B, C, D; A.f = a; B.f = b; C.f = c;
    asm("fma.rn.f32x2 %0, %1, %2, %3;" : "=l"(D.u) : "l"(A.u), "l"(B.u), "l"(C.u));
    return D.f;
}
__device__ __forceinline__ float2 add2(float2 a, float2 b) {
    F2U A, B, D; A.f = a; B.f = b;
    asm("add.rn.f32x2 %0, %1, %2;" : "=l"(D.u) : "l"(A.u), "l"(B.u));
    return D.f;
}

// pure memset-style init: uint4 wide fills, nothing else
__global__ void k_init() {
    int i = blockIdx.x * blockDim.x + threadIdx.x;
    const unsigned INF = 0x7F800000u;
    if (i < (2*NH)/4) ((uint4*)g_dh)[i] = make_uint4(INF, INF, INF, INF);  // 55120
    if (i < (2*NO)/4) ((uint4*)g_do)[i] = make_uint4(INF, INF, INF, INF);  // 16384
    if (i < 8)  g_acc[i] = 0.0;
    if (i == 8) g_done = 0u;
}

__global__ void __launch_bounds__(TPB) k_pair(const float* __restrict__ h,
                                              const float* __restrict__ o,
                                              const float* __restrict__ gh,
                                              const float* __restrict__ go) {
    __shared__ float4   sP[J2];        // {ox.x, ox.y, oy.x, oy.y} (two objects packed, pre-negated *2)
    __shared__ float4   sQ[J2];        // {oz.x, oz.y, ow.x, ow.y}
    __shared__ unsigned sColW[NW][JT]; // per-warp column mins: plain STS, no atomics
    const int ds = blockIdx.z, b = blockIdx.y;
    const int rc = blockIdx.x / JCHUNKS, jc = blockIdx.x % JCHUNKS;
    const int t  = threadIdx.x;
    const int w  = t >> 5;

    // stage objects directly from raw input: obj tile is 256*3 contiguous floats
    // TPB == J2: every thread packs two objects
    const float* OB = (ds ? go : o) + (size_t)(b * VO + jc * JT) * 3;
    {
        const float2* p2 = (const float2*)(OB + 6 * t);   // 8B-aligned
        float2 f0 = p2[0], f1 = p2[1], f2 = p2[2];        // [xA yA | zA xB | yB zB]
        float xA = f0.x, yA = f0.y, zA = f1.x;
        float xB = f1.y, yB = f2.x, zB = f2.y;
        float wA = fmaf(xA, xA, fmaf(yA, yA, zA * zA));
        float wB = fmaf(xB, xB, fmaf(yB, yB, zB * zB));
        sP[t] = make_float4(-2.f*xA, -2.f*xB, -2.f*yA, -2.f*yB);
        sQ[t] = make_float4(-2.f*zA, -2.f*zB, wA, wB);
    }

    const float* H = (ds ? gh : h) + (size_t)b * VH * 3;
    float2 hx2[RPT], hy2[RPT], hz2[RPT], hh2[RPT];
    float rA[RPT], rB[RPT];   // per-half row-min accumulators (q-space)
    const int row0 = rc * ROWCHUNK + t;
#pragma unroll
    for (int k = 0; k < RPT; k++) {
        int row = row0 + k * TPB;
        float x = 0.f, y = 0.f, z = 0.f, s = CUDART_INF_F;
        if (row < VH) {
            x = H[row*3+0]; y = H[row*3+1]; z = H[row*3+2];
            s = fmaf(x, x, fmaf(y, y, z*z));
        }
        hx2[k] = make_float2(x, x);
        hy2[k] = make_float2(y, y);
        hz2[k] = make_float2(z, z);
        hh2[k] = make_float2(s, s);   // +inf for invalid rows -> never wins col-min
        rA[k] = CUDART_INF_F; rB[k] = CUDART_INF_F;
    }
    __syncthreads();

#define UNR 4
#pragma unroll 1
    for (int j0 = 0; j0 < J2; j0 += UNR) {
        // batch smem loads: 2 LDS.128 per j2 (operand pairs usable directly as f32x2)
        float4 vP[UNR], vQ[UNR];
#pragma unroll
        for (int u = 0; u < UNR; u++) { vP[u] = sP[j0+u]; vQ[u] = sQ[j0+u]; }
#pragma unroll
        for (int u = 0; u < UNR; u++) {
            float2 ox = make_float2(vP[u].x, vP[u].y);
            float2 oy = make_float2(vP[u].z, vP[u].w);
            float2 oz = make_float2(vQ[u].x, vQ[u].y);
            float2 ow = make_float2(vQ[u].z, vQ[u].w);
            float cmA = CUDART_INF_F, cmB = CUDART_INF_F;
#pragma unroll
            for (int k = 0; k < RPT; k++) {
                float2 q2 = fma2(hz2[k], oz, ow);   // oo - 2 h·o (two objects)
                q2 = fma2(hy2[k], oy, q2);
                q2 = fma2(hx2[k], ox, q2);
                rA[k] = fminf(rA[k], q2.x);         // row-min in q-space
                rB[k] = fminf(rB[k], q2.y);
                float2 c2 = add2(q2, hh2[k]);       // full d^2 for col-min
                cmA = fminf(cmA, c2.x);
                cmB = fminf(cmB, c2.y);
            }
            // clamp >=0: uint order == float order for the min reductions
            unsigned uA = __reduce_min_sync(0xFFFFFFFFu, __float_as_uint(fmaxf(cmA, 0.f)));
            unsigned uB = __reduce_min_sync(0xFFFFFFFFu, __float_as_uint(fmaxf(cmB, 0.f)));
            if ((t & 31) == 0) {                    // plain STS into this warp's slot
                sColW[w][2*(j0+u)]     = uA;
                sColW[w][2*(j0+u) + 1] = uB;
            }
        }
    }
    __syncthreads();

    // epilogue: combine warp slots per column (conflict-free LDS + IMNMX); each
    // thread handles 2 columns (256 cols / 128 threads), then fire-and-forget REDG.MIN
#pragma unroll
    for (int c = t; c < JT; c += TPB) {
        unsigned m = sColW[0][c];
#pragma unroll
        for (int ww = 1; ww < NW; ww++) m = min(m, sColW[ww][c]);
        atomicMin(&g_do[ds*NO + b*VO + jc*JT + c], m);
    }
#pragma unroll
    for (int k = 0; k < RPT; k++) {
        int row = row0 + k * TPB;
        if (row < VH) {
            float d2 = fmaxf(fminf(rA[k], rB[k]) + hh2[k].x, 0.f);
            atomicMin(&g_dh[ds*NH + b*VH + row], __float_as_uint(d2));
        }
    }
}

#define LOSS_BLOCKS 128

__global__ void k_loss(float* out) {
    const int dir = blockIdx.y;          // 0 = human rows, 1 = object cols
    const int N   = dir ? NO : NH;       // both even
    const unsigned* arr = dir ? g_do : g_dh;
    const int  NN = dir ? NO : NH;
    float P = 0.f, Spos = 0.f, Sneg = 0.f, Shub = 0.f;
    // two adjacent elements per iteration via uint2 loads (read-only)
    for (int i2 = blockIdx.x * blockDim.x + threadIdx.x; i2 < N/2;
         i2 += LOSS_BLOCKS * blockDim.x) {
        uint2 pv = __ldg((const uint2*)&arr[2*i2]);
        uint2 gv = __ldg((const uint2*)&arr[NN + 2*i2]);
#pragma unroll
        for (int e = 0; e < 2; e++) {
            unsigned pb = e ? pv.y : pv.x, gb = e ? gv.y : gv.x;
            float pd = sqrtf(fmaxf(__uint_as_float(pb), 0.f));
            float gd = sqrtf(fmaxf(__uint_as_float(gb), 0.f));
            bool tpos = gd < 0.2f;
            float z = (0.2f - pd) * 100.f;
            // -log(clip(sigmoid(z))) == clamp(log1p(exp(-z)), 1e-6, -log(1e-6))
            float wv = tpos ? -z : z;
            float l = log1pf(expf(wv));
            l = fminf(fmaxf(l, 1e-6f), 13.8155106f);
            if (tpos) { P += 1.f; Spos += l; } else { Sneg += l; }
            float over = fmaxf(pd - 0.1f, 0.f);
            float hub  = (over < 0.01f) ? (50.f * over * over) : (over - 0.005f);
            if (tpos) Shub += hub;
        }
    }
#pragma unroll
    for (int off = 16; off; off >>= 1) {
        P    += __shfl_down_sync(0xFFFFFFFFu, P,    off);
        Spos += __shfl_down_sync(0xFFFFFFFFu, Spos, off);
        Sneg += __shfl_down_sync(0xFFFFFFFFu, Sneg, off);
        Shub += __shfl_down_sync(0xFFFFFFFFu, Shub, off);
    }
    __shared__ float s[4][8];
    int w = threadIdx.x >> 5, l = threadIdx.x & 31;
    if (l == 0) { s[0][w] = P; s[1][w] = Spos; s[2][w] = Sneg; s[3][w] = Shub; }
    __syncthreads();
    if (threadIdx.x == 0) {
        float a0 = 0, a1 = 0, a2 = 0, a3 = 0;
        int nw = (blockDim.x + 31) >> 5;
        for (int k = 0; k < nw; k++) { a0 += s[0][k]; a1 += s[1][k]; a2 += s[2][k]; a3 += s[3][k]; }
        atomicAdd(&g_acc[dir*4 + 0], (double)a0);
        atomicAdd(&g_acc[dir*4 + 1], (double)a1);
        atomicAdd(&g_acc[dir*4 + 2], (double)a2);
        atomicAdd(&g_acc[dir*4 + 3], (double)a3);
        __threadfence();
        unsigned v = atomicAdd(&g_done, 1u);
        if (v == 2*LOSS_BLOCKS - 1) {    // last block: finalize
            double Ph = g_acc[0], Sph = g_acc[1], Snh = g_acc[2], Shh = g_acc[3];
            double Po = g_acc[4], Spo = g_acc[5], Sno = g_acc[6], Sho = g_acc[7];
            double negh = (double)NH - Ph, nego = (double)NO - Po;
            double pwh = (negh + 1e-6) / (Ph + 1e-6);
            double pwo = (nego + 1e-6) / (Po + 1e-6);
            double bh = (pwh * Sph + Snh) / (double)NH;
            double bo = (pwo * Spo + Sno) / (double)NO;
            double Lbce = 0.5 * (bh + bo);
            double LhH = (Ph > 0.0) ? (Shh / fmax(Ph, 1.0)) : 0.0;
            double LhO = (Po > 0.0) ? (Sho / fmax(Po, 1.0)) : 0.0;
            out[0] = (float)(0.5 * Lbce + (LhH + LhO));
        }
    }
}

extern "C" void kernel_launch(void* const* d_in, const int* in_sizes, int n_in,
                              void* d_out, int out_size) {
    const float* h  = (const float*)d_in[0];
    const float* o  = (const float*)d_in[1];
    const float* gh = (const float*)d_in[2];
    const float* go = (const float*)d_in[3];

    k_init<<<((2*NH)/4 + 255)/256, 256>>>();        // 216 blocks, pure fills
    dim3 gp(RCHUNKS * JCHUNKS, BT, 2);              // 112 x 16 x 2 = 3584 blocks
    k_pair<<<gp, TPB>>>(h, o, gh, go);
    dim3 gl(LOSS_BLOCKS, 2);
    k_loss<<<gl, 256>>>((float*)d_out);
}